// round 1
// baseline (speedup 1.0000x reference)
#include <cuda_runtime.h>
#include <math.h>

// Problem constants
#define BS 16
#define L  8192
#define D  512
#define NROWS (BS * L)        // 131072
#define TAU 2.0f
#define NEG -10000.0f

// Scratch: logits [BS*L, 2]  (1 MB, device global — no allocation)
__device__ float g_logits[NROWS * 2];

// ---------------------------------------------------------------------------
// Kernel 1: GEMV  logits[row][c] = dot(x[row,:], W[:,c]) + b[c]
// One warp per row (grid-stride). Fully coalesced float4 loads of x.
// W (512x2 = 4KB) staged via shared, then per-lane slice held in registers.
// ---------------------------------------------------------------------------
__global__ void __launch_bounds__(256) gemv_logits_kernel(
    const float* __restrict__ x,
    const float* __restrict__ W,
    const float* __restrict__ bias)
{
    __shared__ float sW[D * 2];
    int tid = threadIdx.x;
    for (int i = tid; i < D * 2; i += blockDim.x) sW[i] = W[i];
    __syncthreads();

    int lane = tid & 31;
    int warp = tid >> 5;

    // Per-lane W registers: lane covers d = lane*4 + k*128 + j, k=0..3, j=0..3
    float w0[16], w1[16];
#pragma unroll
    for (int k = 0; k < 4; k++) {
#pragma unroll
        for (int j = 0; j < 4; j++) {
            int d = lane * 4 + k * 128 + j;
            w0[k * 4 + j] = sW[d * 2 + 0];
            w1[k * 4 + j] = sW[d * 2 + 1];
        }
    }
    float b0 = bias[0], b1 = bias[1];

    int gwarp  = blockIdx.x * (blockDim.x >> 5) + warp;
    int nwarps = gridDim.x * (blockDim.x >> 5);

    for (int row = gwarp; row < NROWS; row += nwarps) {
        const float4* xp = reinterpret_cast<const float4*>(x + (size_t)row * D);
        float a0 = 0.f, a1 = 0.f;
#pragma unroll
        for (int k = 0; k < 4; k++) {
            float4 v = xp[lane + k * 32];
            a0 = fmaf(v.x, w0[k*4+0], a0);
            a0 = fmaf(v.y, w0[k*4+1], a0);
            a0 = fmaf(v.z, w0[k*4+2], a0);
            a0 = fmaf(v.w, w0[k*4+3], a0);
            a1 = fmaf(v.x, w1[k*4+0], a1);
            a1 = fmaf(v.y, w1[k*4+1], a1);
            a1 = fmaf(v.z, w1[k*4+2], a1);
            a1 = fmaf(v.w, w1[k*4+3], a1);
        }
#pragma unroll
        for (int off = 16; off > 0; off >>= 1) {
            a0 += __shfl_down_sync(0xffffffffu, a0, off);
            a1 += __shfl_down_sync(0xffffffffu, a1, off);
        }
        if (lane == 0) {
            g_logits[row * 2 + 0] = a0 + b0;
            g_logits[row * 2 + 1] = a1 + b1;
        }
    }
}

// ---------------------------------------------------------------------------
// Kernel 2: boundary scan as a parallel scan over 4-state transition functions.
//
// State flag ∈ {0,1,2,3}. Per timestep t with logits (l0, l1):
//   u = (l1 > l0)            (boundary decision if unmasked, i.e. flag==0)
//   m = (l1 + NEG > l0)      (boundary decision if masked,   i.e. flag>0)
//   T(0)   = u ? 3 : 0
//   T(f>0) = m ? 3 : f-1
// A function {0..3}->{0..3} packs into 8 bits (2 bits per entry).
// Composition is associative -> Hillis-Steele block scan.
// One block per batch row; 256 threads x 32 timesteps each.
// ---------------------------------------------------------------------------
__device__ __forceinline__ unsigned compose_fn(unsigned first, unsigned second) {
    // result(s) = second(first(s))
    unsigned r = 0;
#pragma unroll
    for (int s = 0; s < 4; s++) {
        unsigned fs = (first >> (2 * s)) & 3u;
        unsigned ss = (second >> (2 * fs)) & 3u;
        r |= ss << (2 * s);
    }
    return r;
}

__global__ void __launch_bounds__(256) boundary_scan_kernel(float* __restrict__ out)
{
    const int b = blockIdx.x;          // batch row
    const int t = threadIdx.x;         // chunk index
    const int CHUNK = L / 256;         // 32

    const float* lg = g_logits + ((size_t)b * L + (size_t)t * CHUNK) * 2;

    // Pass A: compose this chunk's 32 transitions (track all 4 start states).
    unsigned packed = 0xE4u;           // identity: lanes 0,1,2,3 -> 0,1,2,3
#pragma unroll 4
    for (int i = 0; i < CHUNK; i++) {
        float l0 = lg[2 * i + 0];
        float l1 = lg[2 * i + 1];
        unsigned u = (l1 > l0) ? 1u : 0u;
        unsigned m = ((l1 + NEG) > l0) ? 1u : 0u;
        unsigned np = 0;
#pragma unroll
        for (int s = 0; s < 4; s++) {
            unsigned cur = (packed >> (2 * s)) & 3u;
            unsigned ns = (cur == 0u) ? (u ? 3u : 0u)
                                      : (m ? 3u : (cur - 1u));
            np |= ns << (2 * s);
        }
        packed = np;
    }

    // Hillis-Steele inclusive scan of chunk functions (earliest applied first).
    __shared__ unsigned sf[256];
    sf[t] = packed;
    __syncthreads();
#pragma unroll
    for (int off = 1; off < 256; off <<= 1) {
        unsigned cur  = sf[t];
        unsigned prev = (t >= off) ? sf[t - off] : 0xE4u;
        __syncthreads();
        sf[t] = compose_fn(prev, cur);   // prev chunk runs first
        __syncthreads();
    }

    // Incoming flag for this chunk = exclusive prefix applied to initial 0.
    unsigned flag = (t == 0) ? 0u : (sf[t - 1] & 3u);

    // Replay chunk with the true flag; emit outputs.
    float* outB = out + (size_t)b * L + (size_t)t * CHUNK;
    float* outG = out + (size_t)NROWS + (size_t)b * L + (size_t)t * CHUNK;

#pragma unroll 4
    for (int i = 0; i < CHUNK; i++) {
        float l0 = lg[2 * i + 0];
        float l1 = lg[2 * i + 1];
        float lm1 = (flag > 0u) ? (l1 + NEG) : l1;
        int pred = (lm1 > l0) ? 1 : 0;
        flag = (flag > 0u) ? (flag - 1u) : 0u;
        if (pred) flag = 3u;

        // selected logit is always the max; gathered logp = -log1p(exp((other-max)/TAU))
        float mx    = fmaxf(l0, lm1);
        float other = pred ? l0 : lm1;
        float g = -log1pf(expf((other - mx) * (1.0f / TAU)));

        outB[i] = (float)pred;
        outG[i] = g;
    }
}

// ---------------------------------------------------------------------------
extern "C" void kernel_launch(void* const* d_in, const int* in_sizes, int n_in,
                              void* d_out, int out_size)
{
    const float* x    = (const float*)d_in[0];   // [16, 8192, 512] f32
    // d_in[1] = label (int32) — unused in forward math
    const float* W    = (const float*)d_in[2];   // [512, 2] f32
    const float* bias = (const float*)d_in[3];   // [2] f32
    float* out = (float*)d_out;                  // [131072 boundaries | 131072 gathered]

    gemv_logits_kernel<<<1024, 256>>>(x, W, bias);
    boundary_scan_kernel<<<BS, 256>>>(out);
}

// round 2
// speedup vs baseline: 1.2317x; 1.2317x over previous
#include <cuda_runtime.h>
#include <math.h>

// Problem constants
#define BS 16
#define L  8192
#define D  512
#define NROWS (BS * L)          // 131072 timestep-rows
#define CHUNK 128               // timesteps per block-chunk
#define NCHUNKS (NROWS / CHUNK) // 1024
#define CPR (L / CHUNK)         // 64 chunks per batch row
#define TAU 2.0f
#define NEG -10000.0f
#define FN_ID 0xE4u             // identity fn: 0,1,2,3 -> 0,1,2,3

// Scratch (device globals — no allocation)
__device__ float g_logits[NROWS * 2];          // 1 MB
__device__ unsigned char g_chunkfn[NCHUNKS];   // per-chunk composed transition fn

// fn: {0..3}->{0..3} packed 2 bits/entry. compose(first, second)(s) = second(first(s))
__device__ __forceinline__ unsigned compose_fn(unsigned first, unsigned second) {
    unsigned r = 0;
#pragma unroll
    for (int s = 0; s < 4; s++) {
        unsigned fs = (first >> (2 * s)) & 3u;
        r |= ((second >> (2 * fs)) & 3u) << (2 * s);
    }
    return r;
}

// one-timestep transition function from logits
__device__ __forceinline__ unsigned step_fn(float l0, float l1) {
    unsigned u = (l1 > l0) ? 1u : 0u;                 // decision if flag==0
    unsigned m = ((l1 + NEG) > l0) ? 1u : 0u;         // decision if flag>0
    unsigned e0 = u ? 3u : 0u;
    unsigned e1 = m ? 3u : 0u;
    unsigned e2 = m ? 3u : 1u;
    unsigned e3 = m ? 3u : 2u;
    return e0 | (e1 << 2) | (e2 << 4) | (e3 << 6);
}

// ---------------------------------------------------------------------------
// Kernel 1: GEMV + per-chunk transition-function composition.
// Block b handles rows [b*128, b*128+128). 8 warps x 16 rows each.
// ---------------------------------------------------------------------------
__global__ void __launch_bounds__(256) gemv_chunk_kernel(
    const float* __restrict__ x,
    const float* __restrict__ W,
    const float* __restrict__ bias)
{
    __shared__ float sW[D * 2];
    __shared__ float sL[CHUNK * 2];     // chunk logits in time order
    __shared__ unsigned sf[CHUNK];      // per-step functions / reduction tree

    const int tid  = threadIdx.x;
    const int lane = tid & 31;
    const int warp = tid >> 5;
    const int b    = blockIdx.x;

    for (int i = tid; i < D * 2; i += 256) sW[i] = W[i];
    __syncthreads();

    // per-lane W slice in registers: d = lane*4 + k*128 + j
    float w0[16], w1[16];
#pragma unroll
    for (int k = 0; k < 4; k++)
#pragma unroll
        for (int j = 0; j < 4; j++) {
            int d = lane * 4 + k * 128 + j;
            w0[k * 4 + j] = sW[d * 2 + 0];
            w1[k * 4 + j] = sW[d * 2 + 1];
        }
    const float b0 = bias[0], b1 = bias[1];

    // 16 rows per warp, contiguous in time within the block
#pragma unroll 1
    for (int i = 0; i < 16; i++) {
        int j   = warp * 16 + i;              // local timestep in chunk
        int row = b * CHUNK + j;
        const float4* xp = reinterpret_cast<const float4*>(x + (size_t)row * D);
        float a0 = 0.f, a1 = 0.f;
#pragma unroll
        for (int k = 0; k < 4; k++) {
            float4 v = xp[lane + k * 32];
            a0 = fmaf(v.x, w0[k*4+0], a0); a1 = fmaf(v.x, w1[k*4+0], a1);
            a0 = fmaf(v.y, w0[k*4+1], a0); a1 = fmaf(v.y, w1[k*4+1], a1);
            a0 = fmaf(v.z, w0[k*4+2], a0); a1 = fmaf(v.z, w1[k*4+2], a1);
            a0 = fmaf(v.w, w0[k*4+3], a0); a1 = fmaf(v.w, w1[k*4+3], a1);
        }
#pragma unroll
        for (int off = 16; off > 0; off >>= 1) {
            a0 += __shfl_down_sync(0xffffffffu, a0, off);
            a1 += __shfl_down_sync(0xffffffffu, a1, off);
        }
        if (lane == 0) {
            a0 += b0; a1 += b1;
            sL[j * 2 + 0] = a0;
            sL[j * 2 + 1] = a1;
            g_logits[(size_t)row * 2 + 0] = a0;
            g_logits[(size_t)row * 2 + 1] = a1;
        }
    }
    __syncthreads();

    // compose the chunk's 128 step functions (order-preserving pairwise tree)
    if (tid < CHUNK) sf[tid] = step_fn(sL[tid * 2], sL[tid * 2 + 1]);
    __syncthreads();
#pragma unroll
    for (int n = CHUNK / 2; n >= 1; n >>= 1) {
        unsigned v = 0;
        if (tid < n) v = compose_fn(sf[2 * tid], sf[2 * tid + 1]); // earlier first
        __syncthreads();
        if (tid < n) sf[tid] = v;
        __syncthreads();
    }
    if (tid == 0) g_chunkfn[b] = (unsigned char)sf[0];
}

// ---------------------------------------------------------------------------
// Kernel 2: replay. One block per chunk (1024 blocks x 128 threads).
// Incoming flag = composition of predecessor chunk fns applied to 0;
// in-chunk per-thread flags via Hillis-Steele scan of step functions.
// ---------------------------------------------------------------------------
__global__ void __launch_bounds__(128) replay_kernel(float* __restrict__ out)
{
    const int blk = blockIdx.x;
    const int row = blk / CPR;          // batch row
    const int c   = blk % CPR;          // chunk index within row
    const int t   = threadIdx.x;

    __shared__ unsigned sf[CHUNK];
    __shared__ unsigned s_inflag;

    const size_t base = (size_t)row * L + (size_t)c * CHUNK;

    // per-thread logits for its timestep
    const float l0 = g_logits[(base + t) * 2 + 0];
    const float l1 = g_logits[(base + t) * 2 + 1];

    sf[t] = step_fn(l0, l1);

    // thread 0: serial composition of predecessor chunk functions (<=63)
    if (t == 0) {
        unsigned F = FN_ID;
        const unsigned char* cf = g_chunkfn + row * CPR;
        for (int cc = 0; cc < c; cc++) F = compose_fn(F, (unsigned)cf[cc]);
        s_inflag = F & 3u;   // applied to initial state 0
    }
    __syncthreads();

    // inclusive Hillis-Steele scan over 128 step functions
#pragma unroll
    for (int off = 1; off < CHUNK; off <<= 1) {
        unsigned cur  = sf[t];
        unsigned prev = (t >= off) ? sf[t - off] : FN_ID;
        __syncthreads();
        sf[t] = compose_fn(prev, cur);
        __syncthreads();
    }

    const unsigned inflag = s_inflag;
    // flag entering timestep t = (exclusive prefix)(inflag)
    unsigned flag = (t == 0) ? inflag : ((sf[t - 1] >> (2 * inflag)) & 3u);

    float lm1 = (flag > 0u) ? (l1 + NEG) : l1;
    int pred = (lm1 > l0) ? 1 : 0;

    float mx    = fmaxf(l0, lm1);
    float other = pred ? l0 : lm1;
    float g = -log1pf(expf((other - mx) * (1.0f / TAU)));

    out[base + t]                  = (float)pred;
    out[(size_t)NROWS + base + t]  = g;
}

// ---------------------------------------------------------------------------
extern "C" void kernel_launch(void* const* d_in, const int* in_sizes, int n_in,
                              void* d_out, int out_size)
{
    const float* x    = (const float*)d_in[0];   // [16, 8192, 512] f32
    // d_in[1] = label (int32) — unused
    const float* W    = (const float*)d_in[2];   // [512, 2] f32
    const float* bias = (const float*)d_in[3];   // [2] f32
    float* out = (float*)d_out;

    gemv_chunk_kernel<<<NCHUNKS, 256>>>(x, W, bias);
    replay_kernel<<<NCHUNKS, 128>>>(out);
}

// round 4
// speedup vs baseline: 1.2853x; 1.0435x over previous
#include <cuda_runtime.h>
#include <math.h>

// Problem constants
#define BS 16
#define L  8192
#define D  512
#define NROWS (BS * L)          // 131072 timestep-rows
#define CHUNK 128               // timesteps per chunk
#define NCHUNKS (NROWS / CHUNK) // 1024
#define CPR (L / CHUNK)         // 64 chunks per batch row
#define TAU 2.0f
#define NEG -10000.0f
#define FN_ID 0xE4u             // identity fn: 0,1,2,3 -> 0,1,2,3

// Scratch (device globals — no allocation). SoA logits for coalesced access.
__device__ float g_l0[NROWS];
__device__ float g_l1[NROWS];
__device__ unsigned char g_chunkfn[NCHUNKS];

// fn: {0..3}->{0..3} packed 2 bits/entry. compose(first, second)(s) = second(first(s))
__device__ __forceinline__ unsigned compose_fn(unsigned first, unsigned second) {
    unsigned r = 0;
#pragma unroll
    for (int s = 0; s < 4; s++) {
        unsigned fs = (first >> (2 * s)) & 3u;
        r |= ((second >> (2 * fs)) & 3u) << (2 * s);
    }
    return r;
}

__device__ __forceinline__ unsigned step_fn(float l0, float l1) {
    unsigned u = (l1 > l0) ? 1u : 0u;           // decision if flag==0
    unsigned m = ((l1 + NEG) > l0) ? 1u : 0u;   // decision if flag>0
    unsigned e0 = u ? 3u : 0u;
    unsigned e1 = m ? 3u : 0u;
    unsigned e2 = m ? 3u : 1u;
    unsigned e3 = m ? 3u : 2u;
    return e0 | (e1 << 2) | (e2 << 4) | (e3 << 6);
}

// ---------------------------------------------------------------------------
// Kernel 1: pure GEMV. Warp per row, 2 rows interleaved for MLP.
// ---------------------------------------------------------------------------
__global__ void __launch_bounds__(256) gemv_kernel(
    const float* __restrict__ x,
    const float* __restrict__ W,
    const float* __restrict__ bias)
{
    __shared__ float sW[D * 2];
    int tid = threadIdx.x;
    for (int i = tid; i < D * 2; i += 256) sW[i] = W[i];
    __syncthreads();

    const int lane = tid & 31;
    const int warp = tid >> 5;

    // per-lane W slice: d = lane*4 + k*128 + j
    float w0[16], w1[16];
#pragma unroll
    for (int k = 0; k < 4; k++)
#pragma unroll
        for (int j = 0; j < 4; j++) {
            int d = lane * 4 + k * 128 + j;
            w0[k * 4 + j] = sW[d * 2 + 0];
            w1[k * 4 + j] = sW[d * 2 + 1];
        }
    const float b0 = bias[0], b1 = bias[1];

    const int gwarp  = blockIdx.x * 8 + warp;
    const int nwarps = gridDim.x * 8;            // 8192

#pragma unroll 1
    for (int rA = gwarp; rA < NROWS; rA += 2 * nwarps) {
        const int rB = rA + nwarps;
        const float4* xA = reinterpret_cast<const float4*>(x + (size_t)rA * D);
        const float4* xB = reinterpret_cast<const float4*>(x + (size_t)rB * D);

        float a0A = 0.f, a1A = 0.f, a0B = 0.f, a1B = 0.f;
#pragma unroll
        for (int k = 0; k < 4; k++) {
            float4 vA = xA[lane + k * 32];
            float4 vB = xB[lane + k * 32];
            a0A = fmaf(vA.x, w0[k*4+0], a0A); a1A = fmaf(vA.x, w1[k*4+0], a1A);
            a0A = fmaf(vA.y, w0[k*4+1], a0A); a1A = fmaf(vA.y, w1[k*4+1], a1A);
            a0A = fmaf(vA.z, w0[k*4+2], a0A); a1A = fmaf(vA.z, w1[k*4+2], a1A);
            a0A = fmaf(vA.w, w0[k*4+3], a0A); a1A = fmaf(vA.w, w1[k*4+3], a1A);
            a0B = fmaf(vB.x, w0[k*4+0], a0B); a1B = fmaf(vB.x, w1[k*4+0], a1B);
            a0B = fmaf(vB.y, w0[k*4+1], a0B); a1B = fmaf(vB.y, w1[k*4+1], a1B);
            a0B = fmaf(vB.z, w0[k*4+2], a0B); a1B = fmaf(vB.z, w1[k*4+2], a1B);
            a0B = fmaf(vB.w, w0[k*4+3], a0B); a1B = fmaf(vB.w, w1[k*4+3], a1B);
        }
#pragma unroll
        for (int off = 16; off > 0; off >>= 1) {
            a0A += __shfl_down_sync(0xffffffffu, a0A, off);
            a1A += __shfl_down_sync(0xffffffffu, a1A, off);
            a0B += __shfl_down_sync(0xffffffffu, a0B, off);
            a1B += __shfl_down_sync(0xffffffffu, a1B, off);
        }
        if (lane == 0) {
            g_l0[rA] = a0A + b0;  g_l1[rA] = a1A + b1;
            g_l0[rB] = a0B + b0;  g_l1[rB] = a1B + b1;
        }
    }
}

// ---------------------------------------------------------------------------
// Kernel 2: per-chunk transition function. One warp per 128-step chunk.
// Ordered reduce: ASCENDING offsets so only contiguous segments compose.
// ---------------------------------------------------------------------------
__global__ void __launch_bounds__(256) chunkfn_kernel()
{
    const int lane  = threadIdx.x & 31;
    const int warp  = threadIdx.x >> 5;
    const int chunk = blockIdx.x * 8 + warp;     // grid = 128 blocks

    const size_t base = (size_t)chunk * CHUNK + (size_t)lane * 4;
    float4 v0 = *reinterpret_cast<const float4*>(g_l0 + base);
    float4 v1 = *reinterpret_cast<const float4*>(g_l1 + base);

    unsigned f = step_fn(v0.x, v1.x);
    f = compose_fn(f, step_fn(v0.y, v1.y));
    f = compose_fn(f, step_fn(v0.z, v1.z));
    f = compose_fn(f, step_fn(v0.w, v1.w));

    // ordered tree reduce (ascending off): after off=1 lane i = f_i∘f_{i+1};
    // after off=2 lane 0 = (f0∘f1)∘(f2∘f3); ... lane 0 ends with f0∘...∘f31.
#pragma unroll
    for (int off = 1; off < 32; off <<= 1) {
        unsigned other = __shfl_down_sync(0xffffffffu, f, off);
        f = compose_fn(f, other);
    }
    if (lane == 0) g_chunkfn[chunk] = (unsigned char)f;
}

// ---------------------------------------------------------------------------
// Kernel 3: replay. 1024 blocks x 128 threads. Warp shfl scans.
// ---------------------------------------------------------------------------
__global__ void __launch_bounds__(128) replay_kernel(float* __restrict__ out)
{
    const int blk  = blockIdx.x;
    const int row  = blk / CPR;
    const int c    = blk % CPR;
    const int t    = threadIdx.x;
    const int lane = t & 31;
    const int w    = t >> 5;

    __shared__ unsigned sAgg[4];
    __shared__ unsigned s_inflag;

    const size_t base = (size_t)row * L + (size_t)c * CHUNK;

    const float l0 = g_l0[base + t];
    const float l1 = g_l1[base + t];

    // warp inclusive scan of step functions (time order = lane order)
    unsigned incl = step_fn(l0, l1);
#pragma unroll
    for (int off = 1; off < 32; off <<= 1) {
        unsigned p = __shfl_up_sync(0xffffffffu, incl, off);
        if (lane >= off) incl = compose_fn(p, incl);
    }
    if (lane == 31) sAgg[w] = incl;

    // warp 0: incoming flag = composition of cf[row*CPR .. row*CPR+c-1] applied to 0.
    // 64-wide scan via pair packing in one warp.
    if (w == 0) {
        const unsigned char* cf = g_chunkfn + row * CPR;
        unsigned a = (2 * lane     < c) ? (unsigned)cf[2 * lane]     : FN_ID;
        unsigned b = (2 * lane + 1 < c) ? (unsigned)cf[2 * lane + 1] : FN_ID;
        unsigned v = compose_fn(a, b);
#pragma unroll
        for (int off = 1; off < 32; off <<= 1) {
            unsigned p = __shfl_up_sync(0xffffffffu, v, off);
            if (lane >= off) v = compose_fn(p, v);
        }
        int src = ((c + 1) >> 1) - 1;                 // ceil(c/2)-1 (valid for c>0)
        unsigned F = __shfl_sync(0xffffffffu, v, src < 0 ? 0 : src);
        if (lane == 0) s_inflag = (c == 0) ? 0u : (F & 3u);
    }
    __syncthreads();

    // prefix of preceding warps (<=3 composes, contiguous order)
    unsigned wpre = FN_ID;
#pragma unroll
    for (int ww = 0; ww < 3; ww++)
        if (ww < w) wpre = compose_fn(wpre, sAgg[ww]);

    // exclusive within warp
    unsigned ex = __shfl_up_sync(0xffffffffu, incl, 1);
    if (lane == 0) ex = FN_ID;
    unsigned X = compose_fn(wpre, ex);

    const unsigned inflag = s_inflag;
    unsigned flag = (X >> (2 * inflag)) & 3u;

    float lm1 = (flag > 0u) ? (l1 + NEG) : l1;
    int pred = (lm1 > l0) ? 1 : 0;

    float mx    = fmaxf(l0, lm1);
    float other = pred ? l0 : lm1;
    float g = -log1pf(expf((other - mx) * (1.0f / TAU)));

    out[base + t]                 = (float)pred;
    out[(size_t)NROWS + base + t] = g;
}

// ---------------------------------------------------------------------------
extern "C" void kernel_launch(void* const* d_in, const int* in_sizes, int n_in,
                              void* d_out, int out_size)
{
    const float* x    = (const float*)d_in[0];   // [16, 8192, 512] f32
    // d_in[1] = label (int32) — unused
    const float* W    = (const float*)d_in[2];   // [512, 2] f32
    const float* bias = (const float*)d_in[3];   // [2] f32
    float* out = (float*)d_out;

    gemv_kernel<<<1024, 256>>>(x, W, bias);
    chunkfn_kernel<<<NCHUNKS / 8, 256>>>();
    replay_kernel<<<NCHUNKS, 128>>>(out);
}